// round 6
// baseline (speedup 1.0000x reference)
#include <cuda_runtime.h>
#include <cuda_bf16.h>
#include <cstdint>

// Problem constants
#define BB   32
#define CIN  128
#define C4N  32      // CIN/4
#define COUT 256
#define HH   56
#define WW   56
#define HW   (HH*WW)       // 3136

// Packed scratch (device globals — no allocation)
__device__ int g_xp[BB * C4N * HH * WW];   // [b][c4][h][w], 4 channels packed per int32
__device__ int g_wp[COUT * C4N * 9];       // [co][c4][tap]

// ---------------- pack x: float NCHW -> int8x4 packed [B][C4][H][W] ----------------
__global__ void pack_x_kernel(const float* __restrict__ x) {
    int idx = blockIdx.x * blockDim.x + threadIdx.x;
    if (idx >= BB * C4N * HW) return;
    int hw  = idx % HW;
    int bc4 = idx / HW;
    int c4  = bc4 % C4N;
    int b   = bc4 / C4N;
    const float* xb = x + ((size_t)(b * CIN + c4 * 4)) * HW + hw;
    int v0 = (int)xb[0];
    int v1 = (int)xb[HW];
    int v2 = (int)xb[2 * HW];
    int v3 = (int)xb[3 * HW];
    g_xp[idx] = (v0 & 255) | ((v1 & 255) << 8) | ((v2 & 255) << 16) | ((v3 & 255) << 24);
}

// ---------------- pack w: float OIHW -> int8x4 packed [CO][C4][9] ----------------
__global__ void pack_w_kernel(const float* __restrict__ w) {
    int idx = blockIdx.x * blockDim.x + threadIdx.x;
    if (idx >= COUT * C4N * 9) return;
    int tap = idx % 9;
    int c4  = (idx / 9) % C4N;
    int co  = idx / (9 * C4N);
    const float* wb = w + ((size_t)(co * CIN + c4 * 4)) * 9 + tap;
    int v0 = (int)wb[0];
    int v1 = (int)wb[9];
    int v2 = (int)wb[18];
    int v3 = (int)wb[27];
    g_wp[idx] = (v0 & 255) | ((v1 & 255) << 8) | ((v2 & 255) << 16) | ((v3 & 255) << 24);
}

// ---------------- conv + bias + shift + clamp ----------------
// Block: 4 output rows x 56 cols x 32 couts. 224 threads.
// Thread: 4 consecutive cols x 8 couts (32 int32 accumulators).
// SMEM staged in 2 chunks of 16 c4-groups to stay under 48KB static.
#define CHUNK 16
#define XROW  58                 // padded cols (-1 .. 56)
#define XS_PER_C4 (6 * XROW)     // 6 padded rows

__global__ __launch_bounds__(224) void conv_kernel(
    const float* __restrict__ t, const int* __restrict__ n,
    const int* __restrict__ amin, const int* __restrict__ amax,
    float* __restrict__ out)
{
    __shared__ int xs[CHUNK * XS_PER_C4];   // 16*348*4 = 22272 B
    __shared__ int wss[32 * CHUNK * 9];     // 32*144*4 = 18432 B

    const int tid = threadIdx.x;
    const int rt  = blockIdx.x;   // 0..13 row tile
    const int b   = blockIdx.y;   // batch
    const int cg  = blockIdx.z;   // 0..7 cout tile
    const int r0  = rt * 4;
    const int co0 = cg * 32;

    const int co_grp = tid / 56;          // 0..3
    const int sp     = tid % 56;
    const int r      = sp / 14;           // 0..3 row within tile
    const int wq     = (sp % 14) * 4;     // base output col
    const int co_l0  = co_grp * 8;

    int acc[8][4];
    #pragma unroll
    for (int j = 0; j < 8; j++)
        #pragma unroll
        for (int i = 0; i < 4; i++) acc[j][i] = 0;

    for (int cc = 0; cc < 2; cc++) {
        const int c4base = cc * CHUNK;
        // ---- fill x tile: [c4l][row(6)][col(58)], zero-padded halo ----
        for (int i = tid; i < CHUNK * XS_PER_C4; i += 224) {
            int col = i % XROW;
            int tmp = i / XROW;
            int row = tmp % 6;
            int c4l = tmp / 6;
            int h = r0 + row - 1;
            int w = col - 1;
            int v = 0;
            if (h >= 0 && h < HH && w >= 0 && w < WW)
                v = g_xp[((b * C4N + c4base + c4l) * HH + h) * WW + w];
            xs[i] = v;
        }
        // ---- fill weight tile: wss[co_local*144 + c4l*9 + tap] ----
        for (int i = tid; i < 32 * CHUNK * 9; i += 224) {
            int rest = i % (CHUNK * 9);
            int col  = i / (CHUNK * 9);   // co local
            wss[i] = g_wp[(co0 + col) * (C4N * 9) + c4base * 9 + rest];
        }
        __syncthreads();

        for (int c4l = 0; c4l < CHUNK; c4l++) {
            const int* xb = &xs[c4l * XS_PER_C4];
            const int* wb = &wss[co_l0 * (CHUNK * 9) + c4l * 9];
            #pragma unroll
            for (int kh = 0; kh < 3; kh++) {
                int xv[6];
                const int* xr = xb + (r + kh) * XROW + wq;
                #pragma unroll
                for (int i = 0; i < 6; i++) xv[i] = xr[i];
                #pragma unroll
                for (int kw = 0; kw < 3; kw++) {
                    #pragma unroll
                    for (int j = 0; j < 8; j++) {
                        int wv = wb[j * (CHUNK * 9) + kh * 3 + kw];
                        #pragma unroll
                        for (int i = 0; i < 4; i++)
                            acc[j][i] = __dp4a(xv[kw + i], wv, acc[j][i]);
                    }
                }
            }
        }
        __syncthreads();
    }

    // ---- epilogue: bias, arithmetic right shift, clamp, FLOAT32 store ----
    const int h = r0 + r;
    #pragma unroll
    for (int j = 0; j < 8; j++) {
        const int co = co0 + co_l0 + j;
        const int bias = __float2int_rn(__ldg(&t[co]));
        const int sh   = -__ldg(&n[co]);
        const int lo   = __ldg(&amin[co]);
        const int hi   = __ldg(&amax[co]);
        float4 pk;
        {
            int y0 = (acc[j][0] + bias) >> sh;
            int y1 = (acc[j][1] + bias) >> sh;
            int y2 = (acc[j][2] + bias) >> sh;
            int y3 = (acc[j][3] + bias) >> sh;
            y0 = max(lo, min(hi, y0));
            y1 = max(lo, min(hi, y1));
            y2 = max(lo, min(hi, y2));
            y3 = max(lo, min(hi, y3));
            pk.x = (float)y0;
            pk.y = (float)y1;
            pk.z = (float)y2;
            pk.w = (float)y3;
        }
        *reinterpret_cast<float4*>(out + (((size_t)(b * COUT + co) * HH + h) * WW + wq)) = pk;
    }
}

extern "C" void kernel_launch(void* const* d_in, const int* in_sizes, int n_in,
                              void* d_out, int out_size) {
    (void)in_sizes; (void)n_in; (void)out_size;
    const float* x    = (const float*)d_in[0];
    const float* w    = (const float*)d_in[1];
    const float* t    = (const float*)d_in[2];
    const int*   n    = (const int*)d_in[3];
    const int*   amin = (const int*)d_in[4];
    const int*   amax = (const int*)d_in[5];
    float* out        = (float*)d_out;

    const int nx = BB * C4N * HW;
    pack_x_kernel<<<(nx + 255) / 256, 256>>>(x);
    const int nw = COUT * C4N * 9;
    pack_w_kernel<<<(nw + 255) / 256, 256>>>(w);

    dim3 grid(14, BB, 8);
    conv_kernel<<<grid, 224>>>(t, n, amin, amax, out);
}

// round 15
// speedup vs baseline: 1.0633x; 1.0633x over previous
#include <cuda_runtime.h>
#include <cstdint>

#define BB   32
#define CIN  128
#define COUT 256
#define HH   56
#define WW   56
#define HW   (HH*WW)

// Packed scratch (device globals — no allocation)
__device__ int g_xn[BB * HH * WW * 32];   // NHWC int8: [b][h][w][cin/4], 128B per pixel
__device__ int g_wp2[COUT * 9 * 32];      // [co][tap][cin/4], 128B per (co,tap)

// ---------------- pack x: float NCHW -> NHWC int8 ----------------
__global__ __launch_bounds__(256) void pack_x_kernel(const float* __restrict__ x) {
    __shared__ __align__(16) unsigned char sx[WW * 132];
    int bh = blockIdx.x;                 // b*HH + h
    int b = bh / HH, h = bh % HH;
    const float* xb = x + (size_t)b * CIN * HW + (size_t)h * WW;
    for (int i = threadIdx.x; i < CIN * WW; i += 256) {
        int w = i % WW, c = i / WW;
        int v = (int)xb[(size_t)c * HW + w];
        sx[w * 132 + c] = (unsigned char)v;
    }
    __syncthreads();
    int4* dst = reinterpret_cast<int4*>(g_xn) + (size_t)bh * WW * 8;
    for (int k = threadIdx.x; k < WW * 8; k += 256) {
        int w = k >> 3, c16 = k & 7;
        const unsigned int* s = reinterpret_cast<const unsigned int*>(sx + w * 132 + c16 * 16);
        int4 v; v.x = s[0]; v.y = s[1]; v.z = s[2]; v.w = s[3];
        dst[w * 8 + c16] = v;
    }
}

// ---------------- pack w: float OIHW -> [co][tap][c4] ----------------
__global__ void pack_w_kernel(const float* __restrict__ w) {
    int idx = blockIdx.x * 256 + threadIdx.x;
    if (idx >= COUT * 9 * 32) return;
    int c4 = idx & 31;
    int tap = (idx >> 5) % 9;
    int co = idx / 288;
    const float* p = w + ((size_t)co * CIN + c4 * 4) * 9 + tap;
    int v0 = (int)p[0], v1 = (int)p[9], v2 = (int)p[18], v3 = (int)p[27];
    g_wp2[idx] = (v0 & 255) | ((v1 & 255) << 8) | ((v2 & 255) << 16) | ((v3 & 255) << 24);
}

// ---------------- IMMA conv ----------------
// CTA: 4 output rows (M=224) x 128 couts.  grid (14, 32, 2), 448 threads.
#define WP    144                 // smem pixel / weight-row pitch (conflict-free for ldmatrix)
#define RS    (58 * WP)           // act smem h-row pitch (8352)
#define ACTSZ (6 * RS)            // 50112
#define WBUF  (128 * WP)          // 18432 per weight buffer
#define SMEMT (ACTSZ + 2 * WBUF)  // 86976

__device__ __forceinline__ uint32_t smem_u32(const void* p) {
    uint32_t a;
    asm("{ .reg .u64 t; cvta.to.shared.u64 t, %1; cvt.u32.u64 %0, t; }" : "=r"(a) : "l"(p));
    return a;
}
__device__ __forceinline__ void cp16(uint32_t dst, const void* src, int pred) {
    asm volatile("cp.async.ca.shared.global [%0], [%1], 16, %2;"
                 :: "r"(dst), "l"(src), "r"(pred ? 16 : 0) : "memory");
}
#define CP_COMMIT() asm volatile("cp.async.commit_group;" ::: "memory")
#define CP_WAIT0()  asm volatile("cp.async.wait_group 0;" ::: "memory")

#define LDSM4(r0, r1, r2, r3, addr) \
    asm volatile("ldmatrix.sync.aligned.m8n8.x4.shared.b16 {%0,%1,%2,%3}, [%4];" \
                 : "=r"(r0), "=r"(r1), "=r"(r2), "=r"(r3) : "r"(addr))

#define MMA_S8(d, a, b0, b1) \
    asm volatile("mma.sync.aligned.m16n8k32.row.col.s32.s8.s8.s32 " \
                 "{%0,%1,%2,%3}, {%4,%5,%6,%7}, {%8,%9}, {%0,%1,%2,%3};" \
                 : "+r"((d)[0]), "+r"((d)[1]), "+r"((d)[2]), "+r"((d)[3]) \
                 : "r"((a)[0]), "r"((a)[1]), "r"((a)[2]), "r"((a)[3]), "r"(b0), "r"(b1))

__global__ __launch_bounds__(448, 1) void conv_imma_kernel(
    const float* __restrict__ t, const int* __restrict__ n,
    const int* __restrict__ amin, const int* __restrict__ amax,
    float* __restrict__ out)
{
    extern __shared__ __align__(16) char smem[];
    const uint32_t act = smem_u32(smem);
    const uint32_t ws  = act + ACTSZ;

    const int tid = threadIdx.x, wid = tid >> 5, lane = tid & 31;
    const int h0 = blockIdx.x * 4, b = blockIdx.y, half = blockIdx.z;

    // ---- stage activations (6 halo rows x 58 pixels x 128B) via cp.async ----
    {
        const char* xsrc = (const char*)g_xn;
        for (int ch = tid; ch < 6 * 58 * 8; ch += 448) {
            int cw = ch & 7, p = ch >> 3;
            int hr = p / 58, wp = p % 58;
            int h = h0 + hr - 1, w = wp - 1;
            int ok = (h >= 0 && h < HH && w >= 0 && w < WW);
            const char* src = xsrc + ((size_t)((b * HH + (ok ? h : 0)) * WW + (ok ? w : 0))) * 128 + cw * 16;
            cp16(act + hr * RS + wp * WP + cw * 16, src, ok);
        }
    }
    // ---- stage weights for tap 0 into buffer 0 ----
    {
        const char* wsrc = (const char*)g_wp2;
        for (int ch = tid; ch < 128 * 8; ch += 448) {
            int cw = ch & 7, co = ch >> 3;
            cp16(ws + co * WP + cw * 16,
                 wsrc + (size_t)((half * 128 + co) * 9 + 0) * 128 + cw * 16, 1);
        }
    }
    CP_COMMIT();

    // ---- per-warp / per-lane geometry ----
    const int warp_m = wid % 7, warp_n = wid / 7;
    const int m0 = warp_m * 32, n0 = warp_n * 64;

    const int rsel   = (lane < 16) ? lane : (lane - 16);   // 0..15
    const int half16 = (lane >= 16) ? 16 : 0;
    uint32_t abase[2];
    #pragma unroll
    for (int ma = 0; ma < 2; ma++) {
        int s = m0 + ma * 16 + rsel;
        abase[ma] = act + (s / 56) * RS + (s % 56) * WP + half16;
    }
    const int coff  = ((lane >> 4) & 1) * 8 + (lane & 7);
    const int byteb = ((lane >> 3) & 1) * 16;
    uint32_t bbase[4];
    #pragma unroll
    for (int j = 0; j < 4; j++)
        bbase[j] = ws + (n0 + j * 16 + coff) * WP + byteb;

    int d[2][8][4];
    #pragma unroll
    for (int ma = 0; ma < 2; ma++)
        #pragma unroll
        for (int na = 0; na < 8; na++)
            #pragma unroll
            for (int q = 0; q < 4; q++) d[ma][na][q] = 0;

    CP_WAIT0();
    __syncthreads();

    // ---- main loop: 9 taps ----
    for (int tap = 0; tap < 9; tap++) {
        const int kh = tap / 3, kw = tap % 3;
        const uint32_t cur = (tap & 1) * WBUF;
        if (tap < 8) {
            const uint32_t nxt = ((tap + 1) & 1) * WBUF;
            const char* wsrc = (const char*)g_wp2;
            for (int ch = tid; ch < 128 * 8; ch += 448) {
                int cw = ch & 7, co = ch >> 3;
                cp16(ws + nxt + co * WP + cw * 16,
                     wsrc + (size_t)((half * 128 + co) * 9 + tap + 1) * 128 + cw * 16, 1);
            }
        }
        CP_COMMIT();

        const uint32_t a0 = abase[0] + kh * RS + kw * WP;
        const uint32_t a1 = abase[1] + kh * RS + kw * WP;
        #pragma unroll
        for (int kc = 0; kc < 4; kc++) {
            uint32_t af[2][4], bf[4][4];
            LDSM4(af[0][0], af[0][1], af[0][2], af[0][3], a0 + kc * 32);
            LDSM4(af[1][0], af[1][1], af[1][2], af[1][3], a1 + kc * 32);
            #pragma unroll
            for (int j = 0; j < 4; j++)
                LDSM4(bf[j][0], bf[j][1], bf[j][2], bf[j][3], bbase[j] + cur + kc * 32);
            #pragma unroll
            for (int ma = 0; ma < 2; ma++)
                #pragma unroll
                for (int j = 0; j < 4; j++) {
                    MMA_S8(d[ma][j * 2 + 0], af[ma], bf[j][0], bf[j][1]);
                    MMA_S8(d[ma][j * 2 + 1], af[ma], bf[j][2], bf[j][3]);
                }
        }
        CP_WAIT0();
        __syncthreads();
    }

    // ---- epilogue: bias, arithmetic shift, clamp, f32 store ----
    #pragma unroll
    for (int na = 0; na < 8; na++) {
        const int col = n0 + na * 8 + (lane & 3) * 2;   // local cout
        const int co0g = half * 128 + col;
        const int bias0 = __float2int_rn(__ldg(&t[co0g]));
        const int bias1 = __float2int_rn(__ldg(&t[co0g + 1]));
        const int sh0 = -__ldg(&n[co0g]),     sh1 = -__ldg(&n[co0g + 1]);
        const int lo0 = __ldg(&amin[co0g]),   lo1 = __ldg(&amin[co0g + 1]);
        const int hi0 = __ldg(&amax[co0g]),   hi1 = __ldg(&amax[co0g + 1]);
        #pragma unroll
        for (int ma = 0; ma < 2; ma++) {
            int s = m0 + ma * 16 + (lane >> 2);
            #pragma unroll
            for (int g = 0; g < 2; g++) {       // row group: s, s+8
                int ss = s + g * 8;
                int h = h0 + ss / 56, w = ss % 56;
                size_t o0 = ((size_t)(b * COUT + co0g) * HH + h) * WW + w;
                int y0 = (d[ma][na][g * 2 + 0] + bias0) >> sh0;
                int y1 = (d[ma][na][g * 2 + 1] + bias1) >> sh1;
                y0 = max(lo0, min(hi0, y0));
                y1 = max(lo1, min(hi1, y1));
                out[o0] = (float)y0;
                out[o0 + HW] = (float)y1;
            }
        }
    }
}

// ------------------------------------------------------------------
extern "C" void kernel_launch(void* const* d_in, const int* in_sizes, int n_in,
                              void* d_out, int out_size) {
    (void)in_sizes; (void)n_in; (void)out_size;
    const float* x    = (const float*)d_in[0];
    const float* w    = (const float*)d_in[1];
    const float* t    = (const float*)d_in[2];
    const int*   n    = (const int*)d_in[3];
    const int*   amin = (const int*)d_in[4];
    const int*   amax = (const int*)d_in[5];
    float* out        = (float*)d_out;

    pack_x_kernel<<<BB * HH, 256>>>(x);
    pack_w_kernel<<<(COUT * 9 * 32 + 255) / 256, 256>>>(w);

    cudaFuncSetAttribute(conv_imma_kernel,
                         cudaFuncAttributeMaxDynamicSharedMemorySize, SMEMT);
    dim3 grid(14, BB, 2);
    conv_imma_kernel<<<grid, 448, SMEMT>>>(t, n, amin, amax, out);
}

// round 17
// speedup vs baseline: 2.6250x; 2.4686x over previous
#include <cuda_runtime.h>
#include <cuda_fp16.h>
#include <cstdint>

#define BB   32
#define CIN  128
#define COUT 256
#define HH   56
#define WW   56
#define HW   (HH*WW)

// Packed scratch (device globals — no allocation)
__device__ __half g_xh[BB * HH * WW * CIN];   // NHWC fp16: [b][h][w][c], 256B per pixel
__device__ __half g_wh[COUT * 9 * CIN];       // [co][tap][c] fp16, 256B per (co,tap)

// ---------------- fused pack: x -> NHWC fp16, w -> [co][tap][c] fp16 ----------------
#define PACKX_BLOCKS (BB * HH)                 // 1792
#define PACKW_BLOCKS ((COUT * 9 * CIN + 255) / 256)  // 1152

__global__ __launch_bounds__(256) void pack_fused_kernel(
    const float* __restrict__ x, const float* __restrict__ w)
{
    if (blockIdx.x < PACKX_BLOCKS) {
        __shared__ __align__(16) __half sx[WW * 136];
        int bh = blockIdx.x;                 // b*HH + h
        int b = bh / HH, h = bh % HH;
        const float* xb = x + (size_t)b * CIN * HW + (size_t)h * WW;
        for (int i = threadIdx.x; i < CIN * WW; i += 256) {
            int ww = i % WW, c = i / WW;
            sx[ww * 136 + c] = __float2half_rn(xb[(size_t)c * HW + ww]);
        }
        __syncthreads();
        int4* dst = reinterpret_cast<int4*>(g_xh) + (size_t)bh * WW * 16;
        for (int k = threadIdx.x; k < WW * 16; k += 256) {
            int ww = k >> 4, c16 = k & 15;
            dst[ww * 16 + c16] =
                *reinterpret_cast<const int4*>(sx + ww * 136 + c16 * 8);
        }
    } else {
        int idx = (blockIdx.x - PACKX_BLOCKS) * 256 + threadIdx.x;
        if (idx < COUT * 9 * CIN) {
            int c = idx & 127;
            int tap = (idx >> 7) % 9;
            int co = idx / (9 * CIN);
            g_wh[idx] = __float2half_rn(w[((size_t)co * CIN + c) * 9 + tap]);
        }
    }
}

// ---------------- HMMA f16 conv ----------------
// CTA: 4 output rows (M=224) x 128 couts.  grid (14, 32, 2), 448 threads.
#define WPH   272                  // fp16 pixel / weight-row pitch in bytes (272 mod 128 = 16)
#define RSH   (58 * WPH)           // 15776
#define ACTH  (6 * RSH)            // 94656
#define WBH   (128 * WPH)          // 34816 per weight buffer
#define SMEMH (ACTH + 2 * WBH)     // 164288

__device__ __forceinline__ uint32_t smem_u32(const void* p) {
    uint32_t a;
    asm("{ .reg .u64 t; cvta.to.shared.u64 t, %1; cvt.u32.u64 %0, t; }" : "=r"(a) : "l"(p));
    return a;
}
__device__ __forceinline__ void cp16(uint32_t dst, const void* src, int pred) {
    asm volatile("cp.async.ca.shared.global [%0], [%1], 16, %2;"
                 :: "r"(dst), "l"(src), "r"(pred ? 16 : 0) : "memory");
}
#define CP_COMMIT() asm volatile("cp.async.commit_group;" ::: "memory")
#define CP_WAIT0()  asm volatile("cp.async.wait_group 0;" ::: "memory")

#define LDSM4(r0, r1, r2, r3, addr) \
    asm volatile("ldmatrix.sync.aligned.m8n8.x4.shared.b16 {%0,%1,%2,%3}, [%4];" \
                 : "=r"(r0), "=r"(r1), "=r"(r2), "=r"(r3) : "r"(addr))

#define MMA_F16(d, a, b0, b1) \
    asm volatile("mma.sync.aligned.m16n8k16.row.col.f32.f16.f16.f32 " \
                 "{%0,%1,%2,%3}, {%4,%5,%6,%7}, {%8,%9}, {%0,%1,%2,%3};" \
                 : "+f"((d)[0]), "+f"((d)[1]), "+f"((d)[2]), "+f"((d)[3]) \
                 : "r"((a)[0]), "r"((a)[1]), "r"((a)[2]), "r"((a)[3]), "r"(b0), "r"(b1))

__global__ __launch_bounds__(448, 1) void conv_hmma_kernel(
    const float* __restrict__ t, const int* __restrict__ n,
    const int* __restrict__ amin, const int* __restrict__ amax,
    float* __restrict__ out)
{
    extern __shared__ __align__(16) char smem[];
    const uint32_t act = smem_u32(smem);
    const uint32_t ws  = act + ACTH;

    const int tid = threadIdx.x, wid = tid >> 5, lane = tid & 31;
    const int h0 = blockIdx.x * 4, b = blockIdx.y, half = blockIdx.z;

    // ---- stage activations (6 halo rows x 58 pixels x 256B fp16) ----
    {
        const char* xsrc = (const char*)g_xh;
        for (int ch = tid; ch < 6 * 58 * 16; ch += 448) {
            int cw = ch & 15, p = ch >> 4;
            int hr = p / 58, wp = p % 58;
            int h = h0 + hr - 1, w = wp - 1;
            int ok = (h >= 0 && h < HH && w >= 0 && w < WW);
            const char* src = xsrc + ((size_t)((b * HH + (ok ? h : 0)) * WW + (ok ? w : 0))) * 256 + cw * 16;
            cp16(act + hr * RSH + wp * WPH + cw * 16, src, ok);
        }
    }
    // ---- stage weights for tap 0 into buffer 0 ----
    {
        const char* wsrc = (const char*)g_wh;
        for (int ch = tid; ch < 128 * 16; ch += 448) {
            int cw = ch & 15, co = ch >> 4;
            cp16(ws + co * WPH + cw * 16,
                 wsrc + (size_t)((half * 128 + co) * 9 + 0) * 256 + cw * 16, 1);
        }
    }
    CP_COMMIT();

    // ---- per-warp / per-lane geometry ----
    const int warp_m = wid % 7, warp_n = wid / 7;
    const int m0 = warp_m * 32, n0 = warp_n * 64;

    const int rsel   = (lane < 16) ? lane : (lane - 16);   // 0..15
    const int half16 = (lane >= 16) ? 16 : 0;
    uint32_t abase[2];
    #pragma unroll
    for (int ma = 0; ma < 2; ma++) {
        int s = m0 + ma * 16 + rsel;
        abase[ma] = act + (s / 56) * RSH + (s % 56) * WPH + half16;
    }
    const int coff  = ((lane >> 4) & 1) * 8 + (lane & 7);
    const int byteb = ((lane >> 3) & 1) * 16;
    uint32_t bbase[4];
    #pragma unroll
    for (int j = 0; j < 4; j++)
        bbase[j] = ws + (n0 + j * 16 + coff) * WPH + byteb;

    float d[2][8][4];
    #pragma unroll
    for (int ma = 0; ma < 2; ma++)
        #pragma unroll
        for (int na = 0; na < 8; na++)
            #pragma unroll
            for (int q = 0; q < 4; q++) d[ma][na][q] = 0.0f;

    CP_WAIT0();
    __syncthreads();

    // ---- main loop: 9 taps x 8 k-chunks (K=16 f16 each) ----
    for (int tap = 0; tap < 9; tap++) {
        const int kh = tap / 3, kw = tap % 3;
        const uint32_t cur = (tap & 1) * WBH;
        if (tap < 8) {
            const uint32_t nxt = ((tap + 1) & 1) * WBH;
            const char* wsrc = (const char*)g_wh;
            for (int ch = tid; ch < 128 * 16; ch += 448) {
                int cw = ch & 15, co = ch >> 4;
                cp16(ws + nxt + co * WPH + cw * 16,
                     wsrc + (size_t)((half * 128 + co) * 9 + tap + 1) * 256 + cw * 16, 1);
            }
        }
        CP_COMMIT();

        const uint32_t a0 = abase[0] + kh * RSH + kw * WPH;
        const uint32_t a1 = abase[1] + kh * RSH + kw * WPH;
        #pragma unroll
        for (int kc = 0; kc < 8; kc++) {
            uint32_t af[2][4], bf[4][4];
            LDSM4(af[0][0], af[0][1], af[0][2], af[0][3], a0 + kc * 32);
            LDSM4(af[1][0], af[1][1], af[1][2], af[1][3], a1 + kc * 32);
            #pragma unroll
            for (int j = 0; j < 4; j++)
                LDSM4(bf[j][0], bf[j][1], bf[j][2], bf[j][3], bbase[j] + cur + kc * 32);
            #pragma unroll
            for (int ma = 0; ma < 2; ma++)
                #pragma unroll
                for (int j = 0; j < 4; j++) {
                    MMA_F16(d[ma][j * 2 + 0], af[ma], bf[j][0], bf[j][1]);
                    MMA_F16(d[ma][j * 2 + 1], af[ma], bf[j][2], bf[j][3]);
                }
        }
        CP_WAIT0();
        __syncthreads();
    }

    // ---- epilogue: f32->int, bias, arithmetic shift, clamp, f32 store ----
    #pragma unroll
    for (int na = 0; na < 8; na++) {
        const int col = n0 + na * 8 + (lane & 3) * 2;   // local cout
        const int co0g = half * 128 + col;
        const int bias0 = __float2int_rn(__ldg(&t[co0g]));
        const int bias1 = __float2int_rn(__ldg(&t[co0g + 1]));
        const int sh0 = -__ldg(&n[co0g]),     sh1 = -__ldg(&n[co0g + 1]);
        const int lo0 = __ldg(&amin[co0g]),   lo1 = __ldg(&amin[co0g + 1]);
        const int hi0 = __ldg(&amax[co0g]),   hi1 = __ldg(&amax[co0g + 1]);
        #pragma unroll
        for (int ma = 0; ma < 2; ma++) {
            int s = m0 + ma * 16 + (lane >> 2);
            #pragma unroll
            for (int g = 0; g < 2; g++) {       // row group: s, s+8
                int ss = s + g * 8;
                int h = h0 + ss / 56, w = ss % 56;
                size_t o0 = ((size_t)(b * COUT + co0g) * HH + h) * WW + w;
                int y0 = (__float2int_rn(d[ma][na][g * 2 + 0]) + bias0) >> sh0;
                int y1 = (__float2int_rn(d[ma][na][g * 2 + 1]) + bias1) >> sh1;
                y0 = max(lo0, min(hi0, y0));
                y1 = max(lo1, min(hi1, y1));
                out[o0] = (float)y0;
                out[o0 + HW] = (float)y1;
            }
        }
    }
}

// ------------------------------------------------------------------
extern "C" void kernel_launch(void* const* d_in, const int* in_sizes, int n_in,
                              void* d_out, int out_size) {
    (void)in_sizes; (void)n_in; (void)out_size;
    const float* x    = (const float*)d_in[0];
    const float* w    = (const float*)d_in[1];
    const float* t    = (const float*)d_in[2];
    const int*   n    = (const int*)d_in[3];
    const int*   amin = (const int*)d_in[4];
    const int*   amax = (const int*)d_in[5];
    float* out        = (float*)d_out;

    pack_fused_kernel<<<PACKX_BLOCKS + PACKW_BLOCKS, 256>>>(x, w);

    cudaFuncSetAttribute(conv_hmma_kernel,
                         cudaFuncAttributeMaxDynamicSharedMemorySize, SMEMH);
    dim3 grid(14, BB, 2);
    conv_hmma_kernel<<<grid, 448, SMEMH>>>(t, n, amin, amax, out);
}